// round 5
// baseline (speedup 1.0000x reference)
#include <cuda_runtime.h>
#include <cuda_fp16.h>
#include <math.h>

#define N_NODES 8192
#define N_EDGES 32768
#define FN 32
#define FE 16
#define H 73
#define HH (H*H)            // 5329
#define KP 80               // padded K (5 x k16)
#define TW 5402             // T2 logical row width = 73*74
#define TWP 5504            // padded pitch
#define AHW 160             // concat row width: [agg16 (80) | h16 (80)]
#define GGW 512             // gate GEMM output pitch
#define NB 64
#define T_MP 3
#define T_S2S 12

// ---------------- device scratch ----------------
__device__ float g_h[N_NODES * H];
__device__ __half g_ah[N_NODES * AHW];            // cols 0..79 agg16, 80..159 h16
__device__ float g_RH[N_EDGES * H];
__device__ float g_agg[N_NODES * H];
__device__ __half g_T2[(size_t)N_NODES * TWP];    // 90 MB fp16
__device__ __half g_W2e[KP * TWP];
__device__ __half g_Wgru[AHW * GGW];              // block-diag [Wih^T | Whh^T]
__device__ float g_GG[N_NODES * GGW];
__device__ int g_cnt[N_NODES];
__device__ int g_off[N_NODES + 1];
__device__ int g_cur[N_NODES];
__device__ int g_eord[N_EDGES];

__device__ __forceinline__ float sigf(float x) { return 1.0f / (1.0f + expf(-x)); }

__device__ __forceinline__ void ldsm_x4(unsigned &r0, unsigned &r1, unsigned &r2, unsigned &r3, unsigned addr) {
    asm volatile("ldmatrix.sync.aligned.m8n8.x4.shared.b16 {%0,%1,%2,%3},[%4];"
                 : "=r"(r0), "=r"(r1), "=r"(r2), "=r"(r3) : "r"(addr));
}
__device__ __forceinline__ void ldsm_x4t(unsigned &r0, unsigned &r1, unsigned &r2, unsigned &r3, unsigned addr) {
    asm volatile("ldmatrix.sync.aligned.m8n8.x4.trans.shared.b16 {%0,%1,%2,%3},[%4];"
                 : "=r"(r0), "=r"(r1), "=r"(r2), "=r"(r3) : "r"(addr));
}
__device__ __forceinline__ void mma16816(float* d, const unsigned* a, unsigned b0, unsigned b1) {
    asm volatile("mma.sync.aligned.m16n8k16.row.col.f32.f16.f16.f32 "
                 "{%0,%1,%2,%3},{%4,%5,%6,%7},{%8,%9},{%0,%1,%2,%3};"
                 : "+f"(d[0]), "+f"(d[1]), "+f"(d[2]), "+f"(d[3])
                 : "r"(a[0]), "r"(a[1]), "r"(a[2]), "r"(a[3]), "r"(b0), "r"(b1));
}

// ---------------- prepW2: smem-tiled transpose into W2e (+ pad zeroing) ----------
// block i in [0,73): W2e[j, i*74+kk] = W2[kk, i*73+j] (kk<73), b2[i*73+j] (kk=73)
__global__ __launch_bounds__(256) void k_prepW2(const float* __restrict__ W2,
                                                const float* __restrict__ b2) {
    __shared__ float tile[74 * 73];
    int i = blockIdx.x;
    int tid = threadIdx.x;
    for (int idx = tid; idx < 74 * 73; idx += 256) {
        int kk = idx / 73, j = idx % 73;
        tile[idx] = (kk < H) ? W2[(size_t)kk * HH + i * H + j] : b2[i * H + j];
    }
    __syncthreads();
    for (int idx = tid; idx < 73 * 74; idx += 256) {
        int j = idx / 74, kk = idx % 74;
        g_W2e[(size_t)j * TWP + i * 74 + kk] = __float2half(tile[kk * 73 + j]);
    }
    // pad zeroing spread across all blocks: rows j>=73 (7*TWP) + cols >= 5402 (73*102)
    const int PAD1 = 7 * TWP, PADT = PAD1 + 73 * 102;
    for (int p = blockIdx.x * 256 + tid; p < PADT; p += 73 * 256) {
        int j, c;
        if (p < PAD1) { j = 73 + p / TWP; c = p % TWP; }
        else { int q = p - PAD1; j = q / 102; c = TW + q % 102; }
        g_W2e[(size_t)j * TWP + c] = __float2half(0.0f);
    }
}

// ---------------- h0 (+ zero cnt) ----------------
__global__ void k_h0(const float* __restrict__ nf, const float* __restrict__ Win,
                     const float* __restrict__ bin) {
    int idx = blockIdx.x * blockDim.x + threadIdx.x;
    if (idx >= N_NODES * KP) return;
    if (idx < N_NODES) g_cnt[idx] = 0;
    int n = idx / KP, c = idx % KP;
    if (c >= H) { g_ah[n * AHW + KP + c] = __float2half(0.0f); return; }
    const float* x = nf + n * FN;
    float acc = bin[c];
#pragma unroll
    for (int k = 0; k < FN; k++) acc += x[k] * Win[k * H + c];
    g_h[n * H + c] = acc;
    g_ah[n * AHW + KP + c] = __float2half(acc);
}

// ---------------- RH (+ histogram) ----------------
__global__ void k_rh(const float* __restrict__ ef, const float* __restrict__ W1,
                     const float* __restrict__ b1, const int* __restrict__ Esrc) {
    int idx = blockIdx.x * blockDim.x + threadIdx.x;
    if (idx >= N_EDGES * H) return;
    int e = idx / H, c = idx % H;
    if (c == 0) atomicAdd(&g_cnt[Esrc[e]], 1);
    const float* x = ef + e * FE;
    float acc = b1[c];
#pragma unroll
    for (int k = 0; k < FE; k++) acc += x[k] * W1[k * H + c];
    g_RH[idx] = fmaxf(acc, 0.0f);
}

// ---------------- scan ----------------
__global__ __launch_bounds__(1024) void k_scan() {
    __shared__ int sm_[1024];
    int tid = threadIdx.x;
    int base = tid * 8;
    int v[8], s = 0;
#pragma unroll
    for (int i = 0; i < 8; i++) { v[i] = g_cnt[base + i]; s += v[i]; }
    sm_[tid] = s;
    __syncthreads();
    for (int off = 1; off < 1024; off <<= 1) {
        int t = (tid >= off) ? sm_[tid - off] : 0;
        __syncthreads();
        sm_[tid] += t;
        __syncthreads();
    }
    int run = sm_[tid] - s;
#pragma unroll
    for (int i = 0; i < 8; i++) {
        g_off[base + i] = run;
        g_cur[base + i] = run;
        run += v[i];
    }
    if (tid == 1023) g_off[N_NODES] = run;
}

// ---------------- misc: scatter edges + build block-diag GRU weight ----------------
__global__ void k_misc(const int* __restrict__ Esrc, const float* __restrict__ Wih,
                       const float* __restrict__ Whh) {
    int idx = blockIdx.x * blockDim.x + threadIdx.x;
    if (idx < N_EDGES) {
        int p = atomicAdd(&g_cur[Esrc[idx]], 1);
        g_eord[p] = idx;
    }
    if (idx < AHW * GGW) {
        int k = idx >> 9, c = idx & (GGW - 1);
        float v = 0.0f;
        if (k < H && c < 3 * H) v = Wih[(size_t)c * H + k];
        else if (k >= KP && k < KP + H && c >= 224 && c < 224 + 3 * H)
            v = Whh[(size_t)(c - 224) * H + (k - KP)];
        g_Wgru[idx] = __float2half(v);
    }
}

// ---------------- fp16 MMA GEMM: C[M,N] = A[M,KT*16] @ B[KT*16,N] ----------------
// OUT16=1: __half C, unpredicated half2 stores. OUT16=0: float C, predicated.
template <int OUT16, int KT>
__global__ __launch_bounds__(256) void k_hgemm(const __half* __restrict__ A, int lda,
                                               const __half* __restrict__ B, int ldb,
                                               void* __restrict__ Cv, int ldc, int nreal) {
    const int AP = KT * 16 + 8;
    extern __shared__ __half smh[];
    __half* As = smh;                 // [128][AP]
    __half* Bs = smh + 128 * AP;      // [KT*16][136]
    int tid = threadIdx.x;
    int m0 = blockIdx.y * 128;
    int n0 = blockIdx.x * 128;

    for (int idx = tid; idx < 128 * 2 * KT; idx += 256) {
        int r = idx / (2 * KT), c = idx % (2 * KT);
        *reinterpret_cast<uint4*>(&As[r * AP + c * 8]) =
            *reinterpret_cast<const uint4*>(A + (size_t)(m0 + r) * lda + c * 8);
    }
    for (int idx = tid; idx < KT * 256; idx += 256) {
        int k = idx >> 4, c = idx & 15;
        *reinterpret_cast<uint4*>(&Bs[k * 136 + c * 8]) =
            *reinterpret_cast<const uint4*>(B + (size_t)k * ldb + n0 + c * 8);
    }
    __syncthreads();

    int wid = tid >> 5, lane = tid & 31;
    int wm0 = (wid & 3) * 32;
    int wn0 = (wid >> 2) * 64;

    float acc[2][8][4];
#pragma unroll
    for (int i = 0; i < 2; i++)
#pragma unroll
        for (int j = 0; j < 8; j++)
#pragma unroll
            for (int q = 0; q < 4; q++) acc[i][j][q] = 0.0f;

    unsigned a_base = (unsigned)__cvta_generic_to_shared(As);
    unsigned b_base = (unsigned)__cvta_generic_to_shared(Bs);
    int lr = lane & 15, lc = (lane >> 4) * 8;

#pragma unroll
    for (int ks = 0; ks < KT; ks++) {
        int k0 = ks * 16;
        unsigned af[2][4];
#pragma unroll
        for (int mi = 0; mi < 2; mi++) {
            unsigned addr = a_base + (unsigned)(((wm0 + mi * 16 + lr) * AP + k0 + lc) * 2);
            ldsm_x4(af[mi][0], af[mi][1], af[mi][2], af[mi][3], addr);
        }
        unsigned bf[4][4];
#pragma unroll
        for (int nj = 0; nj < 4; nj++) {
            unsigned addr = b_base + (unsigned)(((k0 + lr) * 136 + wn0 + nj * 16 + lc) * 2);
            ldsm_x4t(bf[nj][0], bf[nj][1], bf[nj][2], bf[nj][3], addr);
        }
#pragma unroll
        for (int mi = 0; mi < 2; mi++)
#pragma unroll
            for (int nj = 0; nj < 4; nj++) {
                mma16816(acc[mi][2 * nj], af[mi], bf[nj][0], bf[nj][1]);
                mma16816(acc[mi][2 * nj + 1], af[mi], bf[nj][2], bf[nj][3]);
            }
    }

    int gr = lane >> 2, gc = (lane & 3) * 2;
#pragma unroll
    for (int mi = 0; mi < 2; mi++) {
#pragma unroll
        for (int nj8 = 0; nj8 < 8; nj8++) {
            int col = n0 + wn0 + nj8 * 8 + gc;
#pragma unroll
            for (int rr = 0; rr < 2; rr++) {
                int row = m0 + wm0 + mi * 16 + gr + rr * 8;
                float v0 = acc[mi][nj8][rr * 2], v1 = acc[mi][nj8][rr * 2 + 1];
                if (OUT16) {
                    __half* C = (__half*)Cv;
                    *reinterpret_cast<__half2*>(C + (size_t)row * ldc + col) =
                        __floats2half2_rn(v0, v1);
                } else {
                    float* C = (float*)Cv;
                    if (col + 1 < nreal) {
                        *reinterpret_cast<float2*>(C + (size_t)row * ldc + col) =
                            make_float2(v0, v1);
                    } else if (col < nreal) {
                        C[(size_t)row * ldc + col] = v0;
                    }
                }
            }
        }
    }
}

// ---------------- messages via fp16 T2 ----------------
__global__ __launch_bounds__(96) void k_msg2(const int* __restrict__ Etgt) {
    int src = blockIdx.x;
    int s0 = g_off[src], s1 = g_off[src + 1];
    if (s0 == s1) return;
    __shared__ float rh[8][H];
    __shared__ int tgts[8];
    int tid = threadIdx.x;
    const __half* trow = g_T2 + (size_t)src * TWP;

    for (int base = s0; base < s1; base += 8) {
        int ne = min(8, s1 - base);
        for (int idx = tid; idx < ne * H; idx += 96) {
            int el = idx / H, k = idx - el * H;
            rh[el][k] = g_RH[(size_t)g_eord[base + el] * H + k];
        }
        if (tid < ne) tgts[tid] = Etgt[g_eord[base + tid]];
        __syncthreads();
        if (tid < H) {
            const __half* tp = trow + tid * (H + 1);
            float bterm = __half2float(tp[H]);
            float acc[8];
#pragma unroll
            for (int e = 0; e < 8; e++) acc[e] = bterm;
#pragma unroll 4
            for (int k2 = 0; k2 < 36; k2++) {
                float2 vf = __half22float2(*reinterpret_cast<const __half2*>(tp + 2 * k2));
#pragma unroll
                for (int e = 0; e < 8; e++)
                    if (e < ne) acc[e] += rh[e][2 * k2] * vf.x + rh[e][2 * k2 + 1] * vf.y;
            }
            float v72 = __half2float(tp[72]);
#pragma unroll
            for (int e = 0; e < 8; e++)
                if (e < ne) {
                    acc[e] += rh[e][72] * v72;
                    atomicAdd(&g_agg[(size_t)tgts[e] * H + tid], acc[e]);
                }
        }
        __syncthreads();
    }
}

// ---------------- cvt agg -> fp16 concat (and re-zero agg) ----------------
__global__ void k_cvt_agg() {
    int idx = blockIdx.x * blockDim.x + threadIdx.x;
    if (idx >= N_NODES * KP) return;
    int n = idx / KP, c = idx % KP;
    float v = 0.0f;
    if (c < H) { v = g_agg[n * H + c]; g_agg[n * H + c] = 0.0f; }
    g_ah[n * AHW + c] = __float2half(v);
}

// ---------------- GRU pointwise ----------------
__global__ void k_grupt(const float* __restrict__ bih, const float* __restrict__ bhh) {
    int idx = blockIdx.x * blockDim.x + threadIdx.x;
    if (idx >= N_NODES * KP) return;
    int n = idx / KP, c = idx % KP;
    if (c >= H) { g_ah[n * AHW + KP + c] = __float2half(0.0f); return; }
    const float* G = g_GG + (size_t)n * GGW;
    float r = sigf(G[c] + G[224 + c] + bih[c] + bhh[c]);
    float z = sigf(G[H + c] + G[224 + H + c] + bih[H + c] + bhh[H + c]);
    float nn = tanhf(G[2 * H + c] + bih[2 * H + c] + r * (G[224 + 2 * H + c] + bhh[2 * H + c]));
    float hv = (1.0f - z) * nn + z * g_h[n * H + c];
    g_h[n * H + c] = hv;
    g_ah[n * AHW + KP + c] = __float2half(hv);
}

// ---------------- Set2Set ----------------
#define EVMAX 2048
__global__ __launch_bounds__(256) void k_s2s(const float* __restrict__ Wih,
                                             const float* __restrict__ Whh,
                                             const float* __restrict__ bih,
                                             const float* __restrict__ bhh,
                                             const float* __restrict__ Wout,
                                             const float* __restrict__ bout,
                                             const int* __restrict__ batch,
                                             float* __restrict__ out) {
    extern __shared__ float sm[];
    float* Wa    = sm;
    float* Wb    = Wa + 292 * 73;
    float* bias  = Wb + 292 * 73;
    float* gates = bias + 292;
    float* hh    = gates + 292;
    float* cc    = hh + 73;
    float* rr    = cc + 73;
    float* rsum  = rr + 73;
    float* ev    = rsum + 73;
    float* red   = ev + EVMAX;

    int tid = threadIdx.x;
    int b = blockIdx.x;

    for (int i = tid; i < 292 * 73; i += 256) {
        int g = i / 73, k = i % 73;
        Wa[i] = Wih[(size_t)g * 146 + k] + Whh[(size_t)g * 73 + k];
        Wb[i] = Wih[(size_t)g * 146 + 73 + k];
    }
    for (int i = tid; i < 292; i += 256) bias[i] = bih[i] + bhh[i];
    if (tid < H) { hh[tid] = 0.0f; cc[tid] = 0.0f; rr[tid] = 0.0f; }

    int lo = 0, hi = N_NODES;
    while (lo < hi) { int mid = (lo + hi) >> 1; if (batch[mid] < b) lo = mid + 1; else hi = mid; }
    int s0 = lo;
    hi = N_NODES;
    while (lo < hi) { int mid = (lo + hi) >> 1; if (batch[mid] < b + 1) lo = mid + 1; else hi = mid; }
    int len = lo - s0;
    if (len > EVMAX) len = EVMAX;
    __syncthreads();

    int lane = tid & 31, w = tid >> 5;

    for (int t = 0; t < T_S2S; t++) {
        for (int g = tid; g < 292; g += 256) {
            const float* wa = Wa + g * 73;
            const float* wb = Wb + g * 73;
            float acc = bias[g];
            for (int k = 0; k < H; k++) acc += hh[k] * wa[k] + rr[k] * wb[k];
            gates[g] = acc;
        }
        __syncthreads();
        if (tid < H) {
            float ig = gates[tid], fg = gates[H + tid], gg = gates[2 * H + tid], og = gates[3 * H + tid];
            float c2 = sigf(fg) * cc[tid] + sigf(ig) * tanhf(gg);
            cc[tid] = c2;
            hh[tid] = sigf(og) * tanhf(c2);
        }
        __syncthreads();

        if (len > 0) {
            for (int n = w; n < len; n += 8) {
                const float* hrow = g_h + (size_t)(s0 + n) * H;
                float acc = 0.0f;
                for (int c = lane; c < H; c += 32) acc += hrow[c] * hh[c];
#pragma unroll
                for (int o = 16; o; o >>= 1) acc += __shfl_down_sync(0xffffffffu, acc, o);
                if (lane == 0) ev[n] = acc;
            }
            __syncthreads();
            float m = -INFINITY;
            for (int n = tid; n < len; n += 256) m = fmaxf(m, ev[n]);
#pragma unroll
            for (int o = 16; o; o >>= 1) m = fmaxf(m, __shfl_xor_sync(0xffffffffu, m, o));
            if (lane == 0) red[w] = m;
            __syncthreads();
            if (tid == 0) {
                float mm = red[0];
                for (int i = 1; i < 8; i++) mm = fmaxf(mm, red[i]);
                red[32] = mm;
            }
            __syncthreads();
            m = red[32];
            float s = 0.0f;
            for (int n = tid; n < len; n += 256) { float a = expf(ev[n] - m); ev[n] = a; s += a; }
#pragma unroll
            for (int o = 16; o; o >>= 1) s += __shfl_xor_sync(0xffffffffu, s, o);
            if (lane == 0) red[w] = s;
            __syncthreads();
            if (tid == 0) {
                float ss = 0.0f;
                for (int i = 0; i < 8; i++) ss += red[i];
                red[33] = ss;
            }
            __syncthreads();
            float inv = 1.0f / red[33];
            if (tid < H) rsum[tid] = 0.0f;
            __syncthreads();
            {
                float a0 = 0.0f, a1 = 0.0f, a2 = 0.0f;
                int c0 = lane, c1 = lane + 32, c2 = lane + 64;
                for (int n = w; n < len; n += 8) {
                    float a = ev[n];
                    const float* hrow = g_h + (size_t)(s0 + n) * H;
                    a0 += a * hrow[c0];
                    a1 += a * hrow[c1];
                    if (lane < 9) a2 += a * hrow[c2];
                }
                atomicAdd(&rsum[c0], a0);
                atomicAdd(&rsum[c1], a1);
                if (lane < 9) atomicAdd(&rsum[c2], a2);
            }
            __syncthreads();
            if (tid < H) rr[tid] = rsum[tid] * inv;
            __syncthreads();
        }
    }

    if (tid == 0) {
        float s = bout[0];
        for (int c = 0; c < H; c++) s += hh[c] * Wout[c];
        out[b] = s;
    }
}

// ---------------- launch ----------------
extern "C" void kernel_launch(void* const* d_in, const int* in_sizes, int n_in,
                              void* d_out, int out_size) {
    const float* nf   = (const float*)d_in[0];
    const float* ef   = (const float*)d_in[1];
    const float* Win  = (const float*)d_in[2];
    const float* bin  = (const float*)d_in[3];
    const float* W1   = (const float*)d_in[4];
    const float* b1   = (const float*)d_in[5];
    const float* W2   = (const float*)d_in[6];
    const float* b2   = (const float*)d_in[7];
    const float* gWih = (const float*)d_in[8];
    const float* gWhh = (const float*)d_in[9];
    const float* gbih = (const float*)d_in[10];
    const float* gbhh = (const float*)d_in[11];
    const float* lWih = (const float*)d_in[12];
    const float* lWhh = (const float*)d_in[13];
    const float* lbih = (const float*)d_in[14];
    const float* lbhh = (const float*)d_in[15];
    const float* Wout = (const float*)d_in[16];
    const float* bout = (const float*)d_in[17];
    const int* Esrc   = (const int*)d_in[18];
    const int* Etgt   = (const int*)d_in[19];
    const int* batch  = (const int*)d_in[20];
    float* out = (float*)d_out;

    __half *p_ah, *p_W2e, *p_Wgru, *p_T2;
    float *p_GG;
    cudaGetSymbolAddress((void**)&p_ah, g_ah);
    cudaGetSymbolAddress((void**)&p_W2e, g_W2e);
    cudaGetSymbolAddress((void**)&p_Wgru, g_Wgru);
    cudaGetSymbolAddress((void**)&p_T2, g_T2);
    cudaGetSymbolAddress((void**)&p_GG, g_GG);

    const int SM5 = (128 * 88 + 80 * 136) * 2;     // 44288
    const int SM10 = (128 * 168 + 160 * 136) * 2;  // 86528
    cudaFuncSetAttribute(k_hgemm<1, 5>, cudaFuncAttributeMaxDynamicSharedMemorySize, SM5);
    cudaFuncSetAttribute(k_hgemm<0, 10>, cudaFuncAttributeMaxDynamicSharedMemorySize, SM10);
    size_t s2s_smem = (size_t)(2 * 292 * 73 + 292 + 292 + 4 * 73 + EVMAX + 34) * sizeof(float);
    cudaFuncSetAttribute(k_s2s, cudaFuncAttributeMaxDynamicSharedMemorySize, (int)s2s_smem);

    dim3 gT(TWP / 128, N_NODES / 128);   // 43 x 64
    dim3 gG(4, N_NODES / 128);           // 448-wide gates

    k_prepW2<<<73, 256>>>(W2, b2);                                     // 0
    k_h0<<<(N_NODES * KP + 255) / 256, 256>>>(nf, Win, bin);           // 1
    k_rh<<<(N_EDGES * H + 255) / 256, 256>>>(ef, W1, b1, Esrc);        // 2
    k_hgemm<1, 5><<<gT, 256, SM5>>>(p_ah + KP, AHW, p_W2e, TWP, p_T2, TWP, TWP);  // 3
    k_scan<<<1, 1024>>>();                                             // 4
    k_misc<<<(AHW * GGW + 255) / 256, 256>>>(Esrc, gWih, gWhh);        // 5

    for (int t = 0; t < T_MP; t++) {
        if (t > 0)
            k_hgemm<1, 5><<<gT, 256, SM5>>>(p_ah + KP, AHW, p_W2e, TWP, p_T2, TWP, TWP);
        k_msg2<<<N_NODES, 96>>>(Etgt);
        k_cvt_agg<<<(N_NODES * KP + 255) / 256, 256>>>();
        k_hgemm<0, 10><<<gG, 256, SM10>>>(p_ah, AHW, p_Wgru, GGW, p_GG, GGW, 448);
        k_grupt<<<(N_NODES * KP + 255) / 256, 256>>>(gbih, gbhh);
    }

    k_s2s<<<NB, 256, s2s_smem>>>(lWih, lWhh, lbih, lbhh, Wout, bout, batch, out);
}

// round 6
// speedup vs baseline: 1.0356x; 1.0356x over previous
#include <cuda_runtime.h>
#include <cuda_fp16.h>
#include <math.h>

#define N_NODES 8192
#define N_EDGES 32768
#define FN 32
#define FE 16
#define H 73
#define HH (H*H)            // 5329
#define KP 80               // padded K (5 x k16)
#define SEG 80              // padded per-channel segment width (74 real + 6 zero)
#define TW2 5920            // W2e width: 73*80 = 5840, padded to 37*160
#define AHW 160             // concat row width: [agg16 (80) | h16 (80)]
#define GGW 512             // gate GEMM output pitch
#define NB 64
#define T_MP 3
#define T_S2S 12

// ---------------- device scratch ----------------
__device__ float g_h[N_NODES * H];
__device__ __half g_ah[N_NODES * AHW];            // cols 0..79 agg16, 80..159 h16
__device__ __half g_RHe[N_EDGES * SEG];           // relu(edge MLP), col73=1, 74..79=0
__device__ __half g_RHs[N_EDGES * SEG];           // same, sorted by src
__device__ float g_agg[N_NODES * H];
__device__ __half g_W2e[KP * TW2];
__device__ __half g_Wgru[AHW * GGW];              // block-diag [Wih^T | Whh^T]
__device__ float g_GG[N_NODES * GGW];
__device__ int g_cnt[N_NODES];
__device__ int g_off[N_NODES + 1];
__device__ int g_cur[N_NODES];
__device__ int g_eord[N_EDGES];
__device__ int g_srcS[N_EDGES];
__device__ int g_tgtS[N_EDGES];

__device__ __forceinline__ float sigf(float x) { return 1.0f / (1.0f + expf(-x)); }

__device__ __forceinline__ void ldsm_x4(unsigned &r0, unsigned &r1, unsigned &r2, unsigned &r3, unsigned addr) {
    asm volatile("ldmatrix.sync.aligned.m8n8.x4.shared.b16 {%0,%1,%2,%3},[%4];"
                 : "=r"(r0), "=r"(r1), "=r"(r2), "=r"(r3) : "r"(addr));
}
__device__ __forceinline__ void ldsm_x4t(unsigned &r0, unsigned &r1, unsigned &r2, unsigned &r3, unsigned addr) {
    asm volatile("ldmatrix.sync.aligned.m8n8.x4.trans.shared.b16 {%0,%1,%2,%3},[%4];"
                 : "=r"(r0), "=r"(r1), "=r"(r2), "=r"(r3) : "r"(addr));
}
__device__ __forceinline__ void mma16816(float* d, const unsigned* a, unsigned b0, unsigned b1) {
    asm volatile("mma.sync.aligned.m16n8k16.row.col.f32.f16.f16.f32 "
                 "{%0,%1,%2,%3},{%4,%5,%6,%7},{%8,%9},{%0,%1,%2,%3};"
                 : "+f"(d[0]), "+f"(d[1]), "+f"(d[2]), "+f"(d[3])
                 : "r"(a[0]), "r"(a[1]), "r"(a[2]), "r"(a[3]), "r"(b0), "r"(b1));
}

// ---------------- prepW2: W2e[j, i*80+kk] = W2[kk, i*73+j] / b2 / 0 ----------------
__global__ __launch_bounds__(256) void k_prepW2(const float* __restrict__ W2,
                                                const float* __restrict__ b2) {
    __shared__ float tile[74 * 73];
    int i = blockIdx.x;         // 0..72
    int tid = threadIdx.x;
    for (int idx = tid; idx < 74 * 73; idx += 256) {
        int kk = idx / 73, j = idx % 73;
        tile[idx] = (kk < H) ? W2[(size_t)kk * HH + i * H + j] : b2[i * H + j];
    }
    __syncthreads();
    for (int idx = tid; idx < 73 * SEG; idx += 256) {
        int j = idx / SEG, kk = idx % SEG;
        float v = (kk < 74) ? tile[kk * 73 + j] : 0.0f;
        g_W2e[(size_t)j * TW2 + i * SEG + kk] = __float2half(v);
    }
    // pad zeroing spread across the 73 blocks: rows j>=73 (full width) + cols >= 5840
    const int PAD1 = 7 * TW2, PADT = PAD1 + 73 * 80;
    for (int p = blockIdx.x * 256 + tid; p < PADT; p += 73 * 256) {
        int j, c;
        if (p < PAD1) { j = 73 + p / TW2; c = p % TW2; }
        else { int q = p - PAD1; j = q / 80; c = 5840 + q % 80; }
        g_W2e[(size_t)j * TW2 + c] = __float2half(0.0f);
    }
}

// ---------------- h0 (+ zero cnt, agg) ----------------
__global__ void k_h0(const float* __restrict__ nf, const float* __restrict__ Win,
                     const float* __restrict__ bin) {
    int idx = blockIdx.x * blockDim.x + threadIdx.x;
    if (idx >= N_NODES * KP) return;
    if (idx < N_NODES) g_cnt[idx] = 0;
    if (idx < N_NODES * H) g_agg[idx] = 0.0f;
    int n = idx / KP, c = idx % KP;
    if (c >= H) { g_ah[n * AHW + KP + c] = __float2half(0.0f); return; }
    const float* x = nf + n * FN;
    float acc = bin[c];
#pragma unroll
    for (int k = 0; k < FN; k++) acc += x[k] * Win[k * H + c];
    g_h[n * H + c] = acc;
    g_ah[n * AHW + KP + c] = __float2half(acc);
}

// ---------------- RH ext fp16 (+ histogram) ----------------
__global__ void k_rh(const float* __restrict__ ef, const float* __restrict__ W1,
                     const float* __restrict__ b1, const int* __restrict__ Esrc) {
    int idx = blockIdx.x * blockDim.x + threadIdx.x;
    if (idx >= N_EDGES * SEG) return;
    int e = idx / SEG, c = idx % SEG;
    if (c == 0) atomicAdd(&g_cnt[Esrc[e]], 1);
    float v;
    if (c < H) {
        const float* x = ef + e * FE;
        float acc = b1[c];
#pragma unroll
        for (int k = 0; k < FE; k++) acc += x[k] * W1[k * H + c];
        v = fmaxf(acc, 0.0f);
    } else v = (c == H) ? 1.0f : 0.0f;
    g_RHe[idx] = __float2half(v);
}

// ---------------- scan ----------------
__global__ __launch_bounds__(1024) void k_scan() {
    __shared__ int sm_[1024];
    int tid = threadIdx.x;
    int base = tid * 8;
    int v[8], s = 0;
#pragma unroll
    for (int i = 0; i < 8; i++) { v[i] = g_cnt[base + i]; s += v[i]; }
    sm_[tid] = s;
    __syncthreads();
    for (int off = 1; off < 1024; off <<= 1) {
        int t = (tid >= off) ? sm_[tid - off] : 0;
        __syncthreads();
        sm_[tid] += t;
        __syncthreads();
    }
    int run = sm_[tid] - s;
#pragma unroll
    for (int i = 0; i < 8; i++) {
        g_off[base + i] = run;
        g_cur[base + i] = run;
        run += v[i];
    }
    if (tid == 1023) g_off[N_NODES] = run;
}

// ---------------- misc: scatter edges + build block-diag GRU weight ----------------
__global__ void k_misc(const int* __restrict__ Esrc, const int* __restrict__ Etgt,
                       const float* __restrict__ Wih, const float* __restrict__ Whh) {
    int idx = blockIdx.x * blockDim.x + threadIdx.x;
    if (idx < N_EDGES) {
        int src = Esrc[idx];
        int p = atomicAdd(&g_cur[src], 1);
        g_eord[p] = idx;
        g_srcS[p] = src;
        g_tgtS[p] = Etgt[idx];
    }
    if (idx < AHW * GGW) {
        int k = idx >> 9, c = idx & (GGW - 1);
        float v = 0.0f;
        if (k < H && c < 3 * H) v = Wih[(size_t)c * H + k];
        else if (k >= KP && k < KP + H && c >= 224 && c < 224 + 3 * H)
            v = Whh[(size_t)(c - 224) * H + (k - KP)];
        g_Wgru[idx] = __float2half(v);
    }
}

// ---------------- sort RH rows by src ----------------
__global__ void k_sortRH() {
    int idx = blockIdx.x * blockDim.x + threadIdx.x;
    if (idx >= N_EDGES * SEG) return;
    int p = idx / SEG, c = idx % SEG;
    g_RHs[idx] = g_RHe[(size_t)g_eord[p] * SEG + c];
}

// ---------------- fused T2-GEMM + message epilogue ----------------
// Block: 128 nodes (m) x 160 cols (= channels i0, i0+1). Computes C tile with MMA,
// stages fp16 tile in smem, then for each edge with src in the node range computes
// m[e,i] = sum_{kk<80} RHs[p,kk] * C[src, i*80+kk] and atomically adds to agg[tgt,i].
__global__ __launch_bounds__(256, 2) void k_t2msg(const __half* __restrict__ A) {
    extern __shared__ __half smh[];
    __half* As = smh;               // [128][88]   (22528 B)
    __half* Bs = smh + 128 * 88;    // [80][168]   (26880 B)
    __half* Cs = smh;               // [128][168]  (43008 B) aliases As+Bs after compute
    int tid = threadIdx.x;
    int m0 = blockIdx.y * 128;
    int n0 = blockIdx.x * 160;

    for (int idx = tid; idx < 128 * 10; idx += 256) {
        int r = idx / 10, c = idx % 10;
        *reinterpret_cast<uint4*>(&As[r * 88 + c * 8]) =
            *reinterpret_cast<const uint4*>(A + (size_t)(m0 + r) * AHW + c * 8);
    }
    for (int idx = tid; idx < 80 * 20; idx += 256) {
        int k = idx / 20, c = idx % 20;
        *reinterpret_cast<uint4*>(&Bs[k * 168 + c * 8]) =
            *reinterpret_cast<const uint4*>(g_W2e + (size_t)k * TW2 + n0 + c * 8);
    }
    __syncthreads();

    int wid = tid >> 5, lane = tid & 31;
    int wm0 = (wid & 3) * 32;       // 4 warps along M
    int wn0 = (wid >> 2) * 80;      // 2 warps along N

    float acc[2][10][4];
#pragma unroll
    for (int i = 0; i < 2; i++)
#pragma unroll
        for (int j = 0; j < 10; j++)
#pragma unroll
            for (int q = 0; q < 4; q++) acc[i][j][q] = 0.0f;

    unsigned a_base = (unsigned)__cvta_generic_to_shared(As);
    unsigned b_base = (unsigned)__cvta_generic_to_shared(Bs);
    int lr = lane & 15, lc = (lane >> 4) * 8;

#pragma unroll
    for (int ks = 0; ks < 5; ks++) {
        int k0 = ks * 16;
        unsigned af[2][4];
#pragma unroll
        for (int mi = 0; mi < 2; mi++) {
            unsigned addr = a_base + (unsigned)(((wm0 + mi * 16 + lr) * 88 + k0 + lc) * 2);
            ldsm_x4(af[mi][0], af[mi][1], af[mi][2], af[mi][3], addr);
        }
        unsigned bf[5][4];
#pragma unroll
        for (int nj = 0; nj < 5; nj++) {
            unsigned addr = b_base + (unsigned)(((k0 + lr) * 168 + wn0 + nj * 16 + lc) * 2);
            ldsm_x4t(bf[nj][0], bf[nj][1], bf[nj][2], bf[nj][3], addr);
        }
#pragma unroll
        for (int mi = 0; mi < 2; mi++)
#pragma unroll
            for (int nj = 0; nj < 5; nj++) {
                mma16816(acc[mi][2 * nj], af[mi], bf[nj][0], bf[nj][1]);
                mma16816(acc[mi][2 * nj + 1], af[mi], bf[nj][2], bf[nj][3]);
            }
    }
    __syncthreads();   // all smem reads done; safe to overwrite with C tile

    int gr = lane >> 2, gc = (lane & 3) * 2;
#pragma unroll
    for (int mi = 0; mi < 2; mi++) {
#pragma unroll
        for (int f = 0; f < 10; f++) {
            int col = wn0 + f * 8 + gc;
#pragma unroll
            for (int rr = 0; rr < 2; rr++) {
                int row = wm0 + mi * 16 + gr + rr * 8;
                *reinterpret_cast<__half2*>(&Cs[row * 168 + col]) =
                    __floats2half2_rn(acc[mi][f][rr * 2], acc[mi][f][rr * 2 + 1]);
            }
        }
    }
    __syncthreads();

    // message epilogue
    int p0 = g_off[m0], p1 = g_off[m0 + 128];
    int ch = tid & 1;
    int i = blockIdx.x * 2 + ch;
    if (i < H) {
        for (int p = p0 + (tid >> 1); p < p1; p += 128) {
            int row = g_srcS[p] - m0;
            const __half2* rh = reinterpret_cast<const __half2*>(g_RHs + (size_t)p * SEG);
            const __half2* cr = reinterpret_cast<const __half2*>(&Cs[row * 168 + ch * 80]);
            float accm = 0.0f;
#pragma unroll
            for (int q = 0; q < 40; q++) {
                float2 a = __half22float2(rh[q]);
                float2 c = __half22float2(cr[q]);
                accm += a.x * c.x + a.y * c.y;
            }
            atomicAdd(&g_agg[(size_t)g_tgtS[p] * H + i], accm);
        }
    }
}

// ---------------- gates GEMM: GG[M,448] = ah[M,160] @ Wgru[160,512] ----------------
template <int KT>
__global__ __launch_bounds__(256) void k_hgemm(const __half* __restrict__ A, int lda,
                                               const __half* __restrict__ B, int ldb,
                                               float* __restrict__ C, int ldc, int nreal) {
    const int AP = KT * 16 + 8;
    extern __shared__ __half smh[];
    __half* As = smh;
    __half* Bs = smh + 128 * AP;
    int tid = threadIdx.x;
    int m0 = blockIdx.y * 128;
    int n0 = blockIdx.x * 128;

    for (int idx = tid; idx < 128 * 2 * KT; idx += 256) {
        int r = idx / (2 * KT), c = idx % (2 * KT);
        *reinterpret_cast<uint4*>(&As[r * AP + c * 8]) =
            *reinterpret_cast<const uint4*>(A + (size_t)(m0 + r) * lda + c * 8);
    }
    for (int idx = tid; idx < KT * 256; idx += 256) {
        int k = idx >> 4, c = idx & 15;
        *reinterpret_cast<uint4*>(&Bs[k * 136 + c * 8]) =
            *reinterpret_cast<const uint4*>(B + (size_t)k * ldb + n0 + c * 8);
    }
    __syncthreads();

    int wid = tid >> 5, lane = tid & 31;
    int wm0 = (wid & 3) * 32;
    int wn0 = (wid >> 2) * 64;

    float acc[2][8][4];
#pragma unroll
    for (int i = 0; i < 2; i++)
#pragma unroll
        for (int j = 0; j < 8; j++)
#pragma unroll
            for (int q = 0; q < 4; q++) acc[i][j][q] = 0.0f;

    unsigned a_base = (unsigned)__cvta_generic_to_shared(As);
    unsigned b_base = (unsigned)__cvta_generic_to_shared(Bs);
    int lr = lane & 15, lc = (lane >> 4) * 8;

#pragma unroll
    for (int ks = 0; ks < KT; ks++) {
        int k0 = ks * 16;
        unsigned af[2][4];
#pragma unroll
        for (int mi = 0; mi < 2; mi++) {
            unsigned addr = a_base + (unsigned)(((wm0 + mi * 16 + lr) * AP + k0 + lc) * 2);
            ldsm_x4(af[mi][0], af[mi][1], af[mi][2], af[mi][3], addr);
        }
        unsigned bf[4][4];
#pragma unroll
        for (int nj = 0; nj < 4; nj++) {
            unsigned addr = b_base + (unsigned)(((k0 + lr) * 136 + wn0 + nj * 16 + lc) * 2);
            ldsm_x4t(bf[nj][0], bf[nj][1], bf[nj][2], bf[nj][3], addr);
        }
#pragma unroll
        for (int mi = 0; mi < 2; mi++)
#pragma unroll
            for (int nj = 0; nj < 4; nj++) {
                mma16816(acc[mi][2 * nj], af[mi], bf[nj][0], bf[nj][1]);
                mma16816(acc[mi][2 * nj + 1], af[mi], bf[nj][2], bf[nj][3]);
            }
    }

    int gr = lane >> 2, gc = (lane & 3) * 2;
#pragma unroll
    for (int mi = 0; mi < 2; mi++) {
#pragma unroll
        for (int nj8 = 0; nj8 < 8; nj8++) {
            int col = n0 + wn0 + nj8 * 8 + gc;
#pragma unroll
            for (int rr = 0; rr < 2; rr++) {
                int row = m0 + wm0 + mi * 16 + gr + rr * 8;
                if (col + 1 < nreal)
                    *reinterpret_cast<float2*>(C + (size_t)row * ldc + col) =
                        make_float2(acc[mi][nj8][rr * 2], acc[mi][nj8][rr * 2 + 1]);
                else if (col < nreal)
                    C[(size_t)row * ldc + col] = acc[mi][nj8][rr * 2];
            }
        }
    }
}

// ---------------- cvt agg -> fp16 concat (and re-zero agg) ----------------
__global__ void k_cvt_agg() {
    int idx = blockIdx.x * blockDim.x + threadIdx.x;
    if (idx >= N_NODES * KP) return;
    int n = idx / KP, c = idx % KP;
    float v = 0.0f;
    if (c < H) { v = g_agg[n * H + c]; g_agg[n * H + c] = 0.0f; }
    g_ah[n * AHW + c] = __float2half(v);
}

// ---------------- GRU pointwise ----------------
__global__ void k_grupt(const float* __restrict__ bih, const float* __restrict__ bhh) {
    int idx = blockIdx.x * blockDim.x + threadIdx.x;
    if (idx >= N_NODES * KP) return;
    int n = idx / KP, c = idx % KP;
    if (c >= H) { g_ah[n * AHW + KP + c] = __float2half(0.0f); return; }
    const float* G = g_GG + (size_t)n * GGW;
    float r = sigf(G[c] + G[224 + c] + bih[c] + bhh[c]);
    float z = sigf(G[H + c] + G[224 + H + c] + bih[H + c] + bhh[H + c]);
    float nn = tanhf(G[2 * H + c] + bih[2 * H + c] + r * (G[224 + 2 * H + c] + bhh[2 * H + c]));
    float hv = (1.0f - z) * nn + z * g_h[n * H + c];
    g_h[n * H + c] = hv;
    g_ah[n * AHW + KP + c] = __float2half(hv);
}

// ---------------- Set2Set ----------------
#define EVMAX 2048
__global__ __launch_bounds__(256) void k_s2s(const float* __restrict__ Wih,
                                             const float* __restrict__ Whh,
                                             const float* __restrict__ bih,
                                             const float* __restrict__ bhh,
                                             const float* __restrict__ Wout,
                                             const float* __restrict__ bout,
                                             const int* __restrict__ batch,
                                             float* __restrict__ out) {
    extern __shared__ float sm[];
    float* Wa    = sm;
    float* Wb    = Wa + 292 * 73;
    float* bias  = Wb + 292 * 73;
    float* gates = bias + 292;
    float* hh    = gates + 292;
    float* cc    = hh + 73;
    float* rr    = cc + 73;
    float* rsum  = rr + 73;
    float* ev    = rsum + 73;
    float* red   = ev + EVMAX;

    int tid = threadIdx.x;
    int b = blockIdx.x;

    for (int i = tid; i < 292 * 73; i += 256) {
        int g = i / 73, k = i % 73;
        Wa[i] = Wih[(size_t)g * 146 + k] + Whh[(size_t)g * 73 + k];
        Wb[i] = Wih[(size_t)g * 146 + 73 + k];
    }
    for (int i = tid; i < 292; i += 256) bias[i] = bih[i] + bhh[i];
    if (tid < H) { hh[tid] = 0.0f; cc[tid] = 0.0f; rr[tid] = 0.0f; }

    int lo = 0, hi = N_NODES;
    while (lo < hi) { int mid = (lo + hi) >> 1; if (batch[mid] < b) lo = mid + 1; else hi = mid; }
    int s0 = lo;
    hi = N_NODES;
    while (lo < hi) { int mid = (lo + hi) >> 1; if (batch[mid] < b + 1) lo = mid + 1; else hi = mid; }
    int len = lo - s0;
    if (len > EVMAX) len = EVMAX;
    __syncthreads();

    int lane = tid & 31, w = tid >> 5;

    for (int t = 0; t < T_S2S; t++) {
        for (int g = tid; g < 292; g += 256) {
            const float* wa = Wa + g * 73;
            const float* wb = Wb + g * 73;
            float acc = bias[g];
            for (int k = 0; k < H; k++) acc += hh[k] * wa[k] + rr[k] * wb[k];
            gates[g] = acc;
        }
        __syncthreads();
        if (tid < H) {
            float ig = gates[tid], fg = gates[H + tid], gg = gates[2 * H + tid], og = gates[3 * H + tid];
            float c2 = sigf(fg) * cc[tid] + sigf(ig) * tanhf(gg);
            cc[tid] = c2;
            hh[tid] = sigf(og) * tanhf(c2);
        }
        __syncthreads();

        if (len > 0) {
            for (int n = w; n < len; n += 8) {
                const float* hrow = g_h + (size_t)(s0 + n) * H;
                float acc = 0.0f;
                for (int c = lane; c < H; c += 32) acc += hrow[c] * hh[c];
#pragma unroll
                for (int o = 16; o; o >>= 1) acc += __shfl_down_sync(0xffffffffu, acc, o);
                if (lane == 0) ev[n] = acc;
            }
            __syncthreads();
            float m = -INFINITY;
            for (int n = tid; n < len; n += 256) m = fmaxf(m, ev[n]);
#pragma unroll
            for (int o = 16; o; o >>= 1) m = fmaxf(m, __shfl_xor_sync(0xffffffffu, m, o));
            if (lane == 0) red[w] = m;
            __syncthreads();
            if (tid == 0) {
                float mm = red[0];
                for (int i = 1; i < 8; i++) mm = fmaxf(mm, red[i]);
                red[32] = mm;
            }
            __syncthreads();
            m = red[32];
            float s = 0.0f;
            for (int n = tid; n < len; n += 256) { float a = expf(ev[n] - m); ev[n] = a; s += a; }
#pragma unroll
            for (int o = 16; o; o >>= 1) s += __shfl_xor_sync(0xffffffffu, s, o);
            if (lane == 0) red[w] = s;
            __syncthreads();
            if (tid == 0) {
                float ss = 0.0f;
                for (int i = 0; i < 8; i++) ss += red[i];
                red[33] = ss;
            }
            __syncthreads();
            float inv = 1.0f / red[33];
            if (tid < H) rsum[tid] = 0.0f;
            __syncthreads();
            {
                float a0 = 0.0f, a1 = 0.0f, a2 = 0.0f;
                int c0 = lane, c1 = lane + 32, c2 = lane + 64;
                for (int n = w; n < len; n += 8) {
                    float a = ev[n];
                    const float* hrow = g_h + (size_t)(s0 + n) * H;
                    a0 += a * hrow[c0];
                    a1 += a * hrow[c1];
                    if (lane < 9) a2 += a * hrow[c2];
                }
                atomicAdd(&rsum[c0], a0);
                atomicAdd(&rsum[c1], a1);
                if (lane < 9) atomicAdd(&rsum[c2], a2);
            }
            __syncthreads();
            if (tid < H) rr[tid] = rsum[tid] * inv;
            __syncthreads();
        }
    }

    if (tid == 0) {
        float s = bout[0];
        for (int c = 0; c < H; c++) s += hh[c] * Wout[c];
        out[b] = s;
    }
}

// ---------------- launch ----------------
extern "C" void kernel_launch(void* const* d_in, const int* in_sizes, int n_in,
                              void* d_out, int out_size) {
    const float* nf   = (const float*)d_in[0];
    const float* ef   = (const float*)d_in[1];
    const float* Win  = (const float*)d_in[2];
    const float* bin  = (const float*)d_in[3];
    const float* W1   = (const float*)d_in[4];
    const float* b1   = (const float*)d_in[5];
    const float* W2   = (const float*)d_in[6];
    const float* b2   = (const float*)d_in[7];
    const float* gWih = (const float*)d_in[8];
    const float* gWhh = (const float*)d_in[9];
    const float* gbih = (const float*)d_in[10];
    const float* gbhh = (const float*)d_in[11];
    const float* lWih = (const float*)d_in[12];
    const float* lWhh = (const float*)d_in[13];
    const float* lbih = (const float*)d_in[14];
    const float* lbhh = (const float*)d_in[15];
    const float* Wout = (const float*)d_in[16];
    const float* bout = (const float*)d_in[17];
    const int* Esrc   = (const int*)d_in[18];
    const int* Etgt   = (const int*)d_in[19];
    const int* batch  = (const int*)d_in[20];
    float* out = (float*)d_out;

    __half *p_ah, *p_Wgru;
    float *p_GG;
    cudaGetSymbolAddress((void**)&p_ah, g_ah);
    cudaGetSymbolAddress((void**)&p_Wgru, g_Wgru);
    cudaGetSymbolAddress((void**)&p_GG, g_GG);

    const int SMT = (128 * 88 + 80 * 168) * 2;     // 49408 (>= 128*168*2 = 43008)
    const int SM10 = (128 * 168 + 160 * 136) * 2;  // 86528
    cudaFuncSetAttribute(k_t2msg, cudaFuncAttributeMaxDynamicSharedMemorySize, SMT);
    cudaFuncSetAttribute(k_hgemm<10>, cudaFuncAttributeMaxDynamicSharedMemorySize, SM10);
    size_t s2s_smem = (size_t)(2 * 292 * 73 + 292 + 292 + 4 * 73 + EVMAX + 34) * sizeof(float);
    cudaFuncSetAttribute(k_s2s, cudaFuncAttributeMaxDynamicSharedMemorySize, (int)s2s_smem);

    dim3 gT(TW2 / 160, N_NODES / 128);   // 37 x 64
    dim3 gG(4, N_NODES / 128);           // 448-wide gates

    k_prepW2<<<73, 256>>>(W2, b2);
    k_h0<<<(N_NODES * KP + 255) / 256, 256>>>(nf, Win, bin);
    k_rh<<<(N_EDGES * SEG + 255) / 256, 256>>>(ef, W1, b1, Esrc);
    k_scan<<<1, 1024>>>();
    k_misc<<<(AHW * GGW + 255) / 256, 256>>>(Esrc, Etgt, gWih, gWhh);
    k_sortRH<<<(N_EDGES * SEG + 255) / 256, 256>>>();

    for (int t = 0; t < T_MP; t++) {
        k_t2msg<<<gT, 256, SMT>>>(p_ah + KP);
        k_cvt_agg<<<(N_NODES * KP + 255) / 256, 256>>>();
        k_hgemm<10><<<gG, 256, SM10>>>(p_ah, AHW, p_Wgru, GGW, p_GG, GGW, 448);
        k_grupt<<<(N_NODES * KP + 255) / 256, 256>>>(gbih, gbhh);
    }

    k_s2s<<<NB, 256, s2s_smem>>>(lWih, lWhh, lbih, lbhh, Wout, bout, batch, out);
}